// round 1
// baseline (speedup 1.0000x reference)
#include <cuda_runtime.h>
#include <math.h>
#include <stddef.h>

#define D      512
#define BATCH  4
#define SEQ    1024
#define NTOK   (BATCH*SEQ)          /* 4096 */
#define NEDGE  34
#define NH     8
#define DH     64
#define NELEM  ((size_t)NTOK*(size_t)D)

/* ------------------------------------------------------------------ */
/* Routing table (computed on device each call)                        */
/* ------------------------------------------------------------------ */
struct Route {
    int nsrc, lind, snode, act;
    int q_sel, k_sel, v_sel;
    int ktype, vmode;
    float aw, wq, wk, wv;
    int q_e, q_op, q_inn;
    int k_e, k_op, k_inn;
    int v_e, v_op, v_inn;
};

__device__ Route g_routes[8];
__device__ int   g_processed[8];

/* Scratch buffers (static device globals; no runtime allocation) */
__device__ float g_outs[8*NTOK*D];
__device__ float g_tq [NTOK*D];
__device__ float g_tk [NTOK*D];
__device__ float g_tv [NTOK*D];
__device__ float g_tln[NTOK*D];
__device__ float g_t0 [NTOK*D];
__device__ float g_t1 [NTOK*D];
__device__ float g_t2 [NTOK*D];
__device__ float g_prep[NTOK*D];
__device__ float g_scores[(size_t)BATCH*NH*SEQ*SEQ];   /* 134 MB */

__device__ __forceinline__ float geluf(float x) {
    return 0.5f*x*(1.0f + tanhf(0.7978845608028654f*(x + 0.044715f*x*x*x)));
}
__device__ __forceinline__ float sigmoidf_(float x) {
    return 1.0f/(1.0f+expf(-x));
}

/* ------------------------------------------------------------------ */
/* Routing kernel: exact mirror of reference _routing + softmax weights */
/* ------------------------------------------------------------------ */
__global__ void route_kernel(const float* __restrict__ node_p,
                             const float* __restrict__ edge_p)
{
    if (threadIdx.x != 0 || blockIdx.x != 0) return;
    for (int i = 0; i < 8; i++) g_processed[i] = 0;

    int lind = 0;
    for (int c = 0; c < 8; c++) {
        int nsrc  = (c + 2 < 5) ? c + 2 : 5;
        int snode = c - nsrc;
        int n5    = nsrc * 5;
        Route r;
        r.nsrc = nsrc; r.lind = lind; r.snode = snode;

        /* node act: argmax + softmax weight */
        int act = 0; float bm = node_p[c*8];
        for (int a = 1; a < 8; a++) { float v = node_p[c*8+a]; if (v > bm) { bm = v; act = a; } }
        float ssum = 0.f;
        for (int a = 0; a < 8; a++) ssum += expf(node_p[c*8+a] - bm);
        r.act = act; r.aw = expf(node_p[c*8+act] - bm) / ssum;

        /* edge_p element accessor: channel i, flat index j in [0, n5) */
        #define EPV(i,j) edge_p[(((i)*NEDGE) + lind + (j)/5)*5 + ((j)%5)]

        /* q: first 5 entries (source 0) masked */
        int qs = -1; float qb = 0.f;
        for (int j = 5; j < n5; j++) {
            float v = EPV(0,j);
            if (qs < 0 || v > qb) { qb = v; qs = j; }
        }
        {
            float s = 0.f;
            for (int j = 5; j < n5; j++) s += expf(EPV(0,j) - qb);
            r.wq = expf(EPV(0,qs) - qb) / s;
        }
        r.q_sel = qs;

        r.k_sel = -1; r.v_sel = -1; r.ktype = 0; r.vmode = 0; r.wk = 0.f; r.wv = 0.f;
        if (act < 7) {
            bool kmask = (act > 0);     /* km = qm if act>0 else None */
            int ks = -1; float kb = 0.f;
            for (int j = 0; j < n5; j++) {
                if (kmask && j < 5) continue;
                float v = EPV(1,j);
                if (ks < 0 || v > kb) { kb = v; ks = j; }
            }
            r.k_sel = ks;
            r.ktype = (ks/5 == 0) ? -2 : -1;
            {
                float s = 0.f;
                for (int j = 0; j < n5; j++) {
                    if (kmask && j < 5) continue;
                    s += expf(EPV(1,j) - kb);
                }
                r.wk = expf(EPV(1,ks) - kb) / s;
            }
            if (act < 5) {
                if (act == 0 && r.ktype == -2) {
                    /* first5 mode: argmax + softmax over ep2[:5], unmasked */
                    int vs = 0; float vb = EPV(2,0);
                    for (int j = 1; j < 5; j++) { float v = EPV(2,j); if (v > vb) { vb = v; vs = j; } }
                    float s = 0.f;
                    for (int j = 0; j < 5; j++) s += expf(EPV(2,j) - vb);
                    r.v_sel = vs; r.vmode = 1;
                    r.wv = expf(EPV(2,vs) - vb) / s;
                } else {
                    int vs = -1; float vb = 0.f;
                    for (int j = 0; j < n5; j++) {
                        if (kmask && j < 5) continue;
                        float v = EPV(2,j);
                        if (vs < 0 || v > vb) { vb = v; vs = j; }
                    }
                    float s = 0.f;
                    for (int j = 0; j < n5; j++) {
                        if (kmask && j < 5) continue;
                        s += expf(EPV(2,j) - vb);
                    }
                    r.v_sel = vs; r.vmode = 0;
                    r.wv = expf(EPV(2,vs) - vb) / s;
                }
            }
        }
        #undef EPV

        /* slot decode + processed marks */
        {
            int se = r.q_sel/5; r.q_op = r.q_sel%5; r.q_e = lind+se;
            r.q_inn = (se == 0) ? -2 : snode+se;
            if (r.q_inn >= 0) g_processed[r.q_inn] = 1;
        }
        if (r.k_sel >= 0) {
            int se = r.k_sel/5; r.k_op = r.k_sel%5; r.k_e = lind+se;
            r.k_inn = (se == 0) ? -2 : snode+se;
            if (r.k_inn >= 0) g_processed[r.k_inn] = 1;
        } else { r.k_e = 0; r.k_op = 4; r.k_inn = -2; }
        if (r.v_sel >= 0) {
            int se = r.v_sel/5; r.v_op = r.v_sel%5; r.v_e = lind+se;
            r.v_inn = (se == 0) ? -2 : snode+se;
            if (r.v_inn >= 0) g_processed[r.v_inn] = 1;
        } else { r.v_e = 0; r.v_op = 4; r.v_inn = -2; }

        g_routes[c] = r;
        lind += nsrc;
    }
}

/* ------------------------------------------------------------------ */
/* Edge prep: per-row LN (ops 0-2), copy (op 3), scaled identity (op 4) */
/* grid: NTOK blocks x 128 threads                                      */
/* ------------------------------------------------------------------ */
__global__ void edge_prep_kernel(int c, int role,
                                 const float* __restrict__ inpute,
                                 const float* __restrict__ inputo,
                                 const float* __restrict__ eg,
                                 const float* __restrict__ ebe)
{
    Route r = g_routes[c];
    int sel, e, op, inn; float w;
    if (role == 0)      { sel = r.q_sel; e = r.q_e; op = r.q_op; inn = r.q_inn; w = r.wq; }
    else if (role == 1) { sel = r.k_sel; e = r.k_e; op = r.k_op; inn = r.k_inn; w = r.wk; }
    else {
        sel = r.v_sel; e = r.v_e; op = r.v_op; inn = r.v_inn; w = r.wv;
        if (r.act == 1) return;   /* act1 never reads v; only 'processed' side-effect matters */
    }
    if (sel < 0) return;

    const float* src = (inn == -2) ? inpute : (inn == -1) ? inputo
                       : (g_outs + (size_t)inn*NELEM);
    int row = blockIdx.x, t = threadIdx.x;
    const float* x = src + (size_t)row*D;

    if (op == 4) {
        float* o = ((role == 0) ? g_tq : (role == 1) ? g_tk : g_tv) + (size_t)row*D;
        for (int i = t; i < D; i += 128) o[i] = w * x[i];
        return;
    }
    float* p = g_prep + (size_t)row*D;
    if (op == 3) {
        for (int i = t; i < D; i += 128) p[i] = x[i];
        return;
    }
    /* ops 0..2: LN with edge g/beta */
    __shared__ float red[128];
    float v[4]; float s = 0.f;
    #pragma unroll
    for (int i = 0; i < 4; i++) { v[i] = x[t + i*128]; s += v[i]; }
    red[t] = s; __syncthreads();
    for (int off = 64; off > 0; off >>= 1) { if (t < off) red[t] += red[t+off]; __syncthreads(); }
    float mean = red[0] / (float)D; __syncthreads();
    s = 0.f;
    #pragma unroll
    for (int i = 0; i < 4; i++) { float d = v[i] - mean; s += d*d; }
    red[t] = s; __syncthreads();
    for (int off = 64; off > 0; off >>= 1) { if (t < off) red[t] += red[t+off]; __syncthreads(); }
    float rs = rsqrtf(red[0] / (float)D + 1e-6f);
    #pragma unroll
    for (int i = 0; i < 4; i++) {
        int col = t + i*128;
        p[col] = (v[i] - mean) * rs * eg[(size_t)e*D + col] + ebe[(size_t)e*D + col];
    }
}

/* ------------------------------------------------------------------ */
/* Generic 4096x512x512 GEMM, config resolved on device from routing    */
/* ------------------------------------------------------------------ */
struct GCfg {
    int active;
    const float* A; const float* A2; int amode;     /* 0 plain, 1 relu, 2 A*A2 */
    const float* W; const float* bias;
    float* C; const float* resid;
    float scale; int act;                            /* 0 none, 1 relu, 2 gelu */
    int accum;
};

__device__ __forceinline__ GCfg gemm_cfg(int c, int role,
                                         const float* eW, const float* eb,
                                         const float* nW, const float* nb)
{
    Route r = g_routes[c];
    GCfg g; g.active = 0; g.amode = 0; g.act = 0; g.accum = 0;
    g.scale = 1.f; g.A2 = 0; g.resid = 0; g.bias = 0; g.A = 0; g.W = 0; g.C = 0;

    if (role < 3) {                          /* edge GEMMs */
        int sel, e, op; float w;
        if (role == 0)      { sel = r.q_sel; e = r.q_e; op = r.q_op; w = r.wq; }
        else if (role == 1) { sel = r.k_sel; e = r.k_e; op = r.k_op; w = r.wk; }
        else {
            sel = r.v_sel; e = r.v_e; op = r.v_op; w = r.wv;
            if (r.act == 1) return g;
        }
        if (sel < 0 || op == 4) return g;
        g.active = 1;
        g.A = g_prep;
        g.W = eW + (size_t)e*D*D;
        g.bias = eb + (size_t)e*D;
        g.act = (op == 0) ? 1 : (op == 1) ? 2 : 0;
        g.C = (role == 0) ? g_tq : (role == 1) ? g_tk : g_tv;
        g.scale = w;
        return g;
    }

    const float* W0 = nW + (size_t)c*4*D*D;
    const float* b0 = nb + (size_t)c*4*D;
    int a = r.act;
    if (role == 3) {
        if (a == 0)      { g.active=1; g.A=g_tln; g.W=W0;       g.bias=b0;       g.C=g_t0; }
        else if (a == 1) { g.active=1; g.A=g_tq;  g.W=W0;       g.bias=b0;       g.C=g_t0; g.act=2; }
        else if (a == 3) { g.active=1; g.A=g_tq;  g.W=W0;                        g.C=g_t0; }
    } else if (role == 4) {
        if (a == 0 || a == 1) { g.active=1; g.A=g_tk; g.W=W0+(size_t)D*D; g.bias=b0+D; g.C=g_t1; }
        else if (a == 3)      { g.active=1; g.A=g_tk; g.W=W0+(size_t)D*D;              g.C=g_t0; g.accum=1; }
        else if (a == 5)      { g.active=1; g.A=g_tk; g.W=W0+(size_t)D*D; g.bias=b0+D; g.C=g_t0; g.act=2; }
    } else if (role == 5) {
        if (a == 0)      { g.active=1; g.A=g_tv; g.W=W0+(size_t)2*D*D; g.bias=b0+2*D; g.C=g_t2; }
        else if (a == 3) { g.active=1; g.A=g_tv; g.W=W0+(size_t)2*D*D;                g.C=g_t0; g.accum=1; }
    } else {  /* role 6: final projection */
        if (a == 0) {
            g.active=1; g.A=g_tln; g.W=W0+(size_t)3*D*D; g.bias=b0+3*D;
            g.C=g_outs+(size_t)c*NELEM; g.resid=g_tq; g.scale=r.aw;
        } else if (a == 1) {
            g.active=1; g.A=g_t0; g.amode=2; g.A2=g_t1; g.W=W0+(size_t)3*D*D; g.bias=b0+3*D;
            g.C=g_outs+(size_t)c*NELEM; g.resid=g_tq; g.scale=r.aw;
        } else if (a == 3) {
            g.active=1; g.A=g_t0; g.amode=1; g.W=W0+(size_t)3*D*D; g.bias=b0+3*D;
            g.C=g_outs+(size_t)c*NELEM; g.resid=g_tq; g.scale=r.aw;
        }
    }
    return g;
}

/* grid (8, 64), block 256: BM=BN=64, BK=16, 4x4 per thread */
__global__ void gemm_kernel(int c, int role,
                            const float* __restrict__ eW, const float* __restrict__ eb,
                            const float* __restrict__ nW, const float* __restrict__ nb)
{
    GCfg g = gemm_cfg(c, role, eW, eb, nW, nb);
    if (!g.active) return;

    __shared__ float As[16][64];
    __shared__ float Bs[16][64];
    int tid = threadIdx.x, tr = tid >> 4, tc = tid & 15;
    int rowBase = blockIdx.y * 64, colBase = blockIdx.x * 64;
    float acc[4][4] = {};

    for (int k0 = 0; k0 < D; k0 += 16) {
        #pragma unroll
        for (int i = 0; i < 4; i++) {
            int lin = tid + i*256;
            int m = lin >> 4, kk = lin & 15;
            float a = g.A[(size_t)(rowBase+m)*D + k0 + kk];
            if (g.amode == 1) a = fmaxf(a, 0.f);
            else if (g.amode == 2) a *= g.A2[(size_t)(rowBase+m)*D + k0 + kk];
            As[kk][m] = a;
            int kk2 = lin >> 6, n = lin & 63;
            Bs[kk2][n] = g.W[(size_t)(k0+kk2)*D + colBase + n];
        }
        __syncthreads();
        #pragma unroll
        for (int kk = 0; kk < 16; kk++) {
            float a[4], b[4];
            #pragma unroll
            for (int i = 0; i < 4; i++) a[i] = As[kk][tr*4+i];
            #pragma unroll
            for (int j = 0; j < 4; j++) b[j] = Bs[kk][tc*4+j];
            #pragma unroll
            for (int i = 0; i < 4; i++)
                #pragma unroll
                for (int j = 0; j < 4; j++)
                    acc[i][j] += a[i]*b[j];
        }
        __syncthreads();
    }

    #pragma unroll
    for (int i = 0; i < 4; i++) {
        int row = rowBase + tr*4 + i;
        #pragma unroll
        for (int j = 0; j < 4; j++) {
            int col = colBase + tc*4 + j;
            float v = acc[i][j];
            if (g.bias) v += g.bias[col];
            if (g.act == 1) v = fmaxf(v, 0.f);
            else if (g.act == 2) v = geluf(v);
            size_t idx = (size_t)row*D + col;
            if (g.accum) g.C[idx] += v;
            else {
                if (g.resid) v += g.resid[idx];
                g.C[idx] = g.scale * v;
            }
        }
    }
}

/* ------------------------------------------------------------------ */
/* Node prep: elementwise / LN acts. grid NTOK x 128                    */
/* ------------------------------------------------------------------ */
__global__ void node_prep_kernel(int c, const float* __restrict__ ng,
                                 const float* __restrict__ nbe)
{
    Route r = g_routes[c];
    int a = r.act;
    if (!(a == 0 || a == 2 || a == 4 || a == 6 || a == 7)) return;
    int row = blockIdx.x, t = threadIdx.x;
    size_t base = (size_t)row*D;

    if (a == 4) {
        for (int i = t; i < D; i += 128) {
            float q = g_tq[base+i], k = g_tk[base+i], vv = g_tv[base+i];
            g_outs[(size_t)c*NELEM + base + i] = r.aw * (q * sigmoidf_(k) + vv);
        }
        return;
    }
    if (a == 6) {
        for (int i = t; i < D; i += 128)
            g_outs[(size_t)c*NELEM + base + i] = r.aw * (g_tq[base+i] + g_tk[base+i]);
        return;
    }
    /* LN cases: a==0 (LN(q) -> tln), a==2 (LN(q+k+v) -> outs), a==7 (LN(q) -> outs) */
    __shared__ float red[128];
    float v[4]; float s = 0.f;
    #pragma unroll
    for (int i = 0; i < 4; i++) {
        int col = t + i*128;
        float x = g_tq[base+col];
        if (a == 2) x += g_tk[base+col] + g_tv[base+col];
        v[i] = x; s += x;
    }
    red[t] = s; __syncthreads();
    for (int off = 64; off > 0; off >>= 1) { if (t < off) red[t] += red[t+off]; __syncthreads(); }
    float mean = red[0] / (float)D; __syncthreads();
    s = 0.f;
    #pragma unroll
    for (int i = 0; i < 4; i++) { float d = v[i]-mean; s += d*d; }
    red[t] = s; __syncthreads();
    for (int off = 64; off > 0; off >>= 1) { if (t < off) red[t] += red[t+off]; __syncthreads(); }
    float rs = rsqrtf(red[0] / (float)D + 1e-6f);
    #pragma unroll
    for (int i = 0; i < 4; i++) {
        int col = t + i*128;
        float y = (v[i]-mean)*rs*ng[(size_t)c*D+col] + nbe[(size_t)c*D+col];
        if (a == 0) g_tln[base+col] = y;
        else        g_outs[(size_t)c*NELEM + base + col] = r.aw * y;
    }
}

/* act 5 epilogue: outs = aw*(q + gelu_result) */
__global__ void node_ew_kernel(int c)
{
    Route r = g_routes[c];
    if (r.act != 5) return;
    int row = blockIdx.x, t = threadIdx.x;
    size_t base = (size_t)row*D;
    for (int i = t; i < D; i += 128)
        g_outs[(size_t)c*NELEM + base + i] = r.aw * (g_tq[base+i] + g_t0[base+i]);
}

/* ------------------------------------------------------------------ */
/* Attention (act 0 only)                                              */
/* ------------------------------------------------------------------ */
/* grid (16, 16, 32): x=col tile, y=row tile, z = b*8+h */
__global__ void attn_scores_kernel(int c,
                                   const unsigned char* __restrict__ srcm,
                                   const unsigned char* __restrict__ tgtm)
{
    Route r = g_routes[c];
    if (r.act != 0) return;
    int bh = blockIdx.z; int b = bh >> 3, h = bh & 7;
    const float* Q = g_t0 + (size_t)b*SEQ*D + (size_t)h*DH;
    const float* K = g_t1 + (size_t)b*SEQ*D + (size_t)h*DH;
    const unsigned char* m = ((r.ktype == -2) ? srcm : tgtm) + (size_t)b*SEQ;

    __shared__ float As[16][64];
    __shared__ float Bs[16][64];
    int tid = threadIdx.x, tr = tid >> 4, tc = tid & 15;
    int rowBase = blockIdx.y * 64, colBase = blockIdx.x * 64;
    float acc[4][4] = {};

    for (int k0 = 0; k0 < DH; k0 += 16) {
        #pragma unroll
        for (int i = 0; i < 4; i++) {
            int lin = tid + i*256;
            int mm = lin >> 4, kk = lin & 15;
            As[kk][mm] = Q[(size_t)(rowBase+mm)*D + k0 + kk];
            Bs[kk][mm] = K[(size_t)(colBase+mm)*D + k0 + kk];
        }
        __syncthreads();
        #pragma unroll
        for (int kk = 0; kk < 16; kk++) {
            float a[4], bb[4];
            #pragma unroll
            for (int i = 0; i < 4; i++) a[i] = As[kk][tr*4+i];
            #pragma unroll
            for (int j = 0; j < 4; j++) bb[j] = Bs[kk][tc*4+j];
            #pragma unroll
            for (int i = 0; i < 4; i++)
                #pragma unroll
                for (int j = 0; j < 4; j++)
                    acc[i][j] += a[i]*bb[j];
        }
        __syncthreads();
    }

    float* Sp = g_scores + ((size_t)bh*SEQ + rowBase)*SEQ + colBase;
    #pragma unroll
    for (int i = 0; i < 4; i++)
        #pragma unroll
        for (int j = 0; j < 4; j++) {
            int col = colBase + tc*4 + j;
            float v = acc[i][j] * 0.125f;           /* 1/sqrt(64) */
            if (m[col]) v = -1e9f;
            Sp[(size_t)(tr*4+i)*SEQ + tc*4 + j] = v;
        }
}

/* grid 32768 x 256: one row of 1024 per block */
__global__ void attn_softmax_kernel(int c)
{
    if (g_routes[c].act != 0) return;
    size_t row = blockIdx.x;
    float* p = g_scores + row * (size_t)SEQ;
    int t = threadIdx.x;
    __shared__ float red[256];
    float v[4]; float mx = -1e30f;
    #pragma unroll
    for (int i = 0; i < 4; i++) { v[i] = p[t + i*256]; mx = fmaxf(mx, v[i]); }
    red[t] = mx; __syncthreads();
    for (int off = 128; off > 0; off >>= 1) { if (t < off) red[t] = fmaxf(red[t], red[t+off]); __syncthreads(); }
    float M = red[0]; __syncthreads();
    float e[4]; float s = 0.f;
    #pragma unroll
    for (int i = 0; i < 4; i++) { e[i] = expf(v[i] - M); s += e[i]; }
    red[t] = s; __syncthreads();
    for (int off = 128; off > 0; off >>= 1) { if (t < off) red[t] += red[t+off]; __syncthreads(); }
    float inv = 1.0f / red[0];
    #pragma unroll
    for (int i = 0; i < 4; i++) p[t + i*256] = e[i] * inv;
}

/* grid (16, 32): x = row tile, y = b*8+h. O written head-merged into g_tln */
__global__ void attn_pv_kernel(int c)
{
    Route r = g_routes[c];
    if (r.act != 0) return;
    int bh = blockIdx.y; int b = bh >> 3, h = bh & 7;
    int rowBase = blockIdx.x * 64;
    const float* P = g_scores + (size_t)bh*SEQ*SEQ;
    const float* V = g_t2 + (size_t)b*SEQ*D + (size_t)h*DH;

    __shared__ float As[16][64];
    __shared__ float Bs[16][64];
    int tid = threadIdx.x, tr = tid >> 4, tc = tid & 15;
    float acc[4][4] = {};

    for (int k0 = 0; k0 < SEQ; k0 += 16) {
        #pragma unroll
        for (int i = 0; i < 4; i++) {
            int lin = tid + i*256;
            int mm = lin >> 4, kk = lin & 15;
            As[kk][mm] = P[(size_t)(rowBase+mm)*SEQ + k0 + kk];
            int kk2 = lin >> 6, n = lin & 63;
            Bs[kk2][n] = V[(size_t)(k0+kk2)*D + n];
        }
        __syncthreads();
        #pragma unroll
        for (int kk = 0; kk < 16; kk++) {
            float a[4], bb[4];
            #pragma unroll
            for (int i = 0; i < 4; i++) a[i] = As[kk][tr*4+i];
            #pragma unroll
            for (int j = 0; j < 4; j++) bb[j] = Bs[kk][tc*4+j];
            #pragma unroll
            for (int i = 0; i < 4; i++)
                #pragma unroll
                for (int j = 0; j < 4; j++)
                    acc[i][j] += a[i]*bb[j];
        }
        __syncthreads();
    }

    float* O = g_tln + (size_t)b*SEQ*D + (size_t)h*DH;
    #pragma unroll
    for (int i = 0; i < 4; i++)
        #pragma unroll
        for (int j = 0; j < 4; j++)
            O[(size_t)(rowBase+tr*4+i)*D + tc*4 + j] = acc[i][j];
}

/* ------------------------------------------------------------------ */
/* Final: sum of unprocessed node outputs, output LN. grid NTOK x 128   */
/* ------------------------------------------------------------------ */
__global__ void final_kernel(const float* __restrict__ og,
                             const float* __restrict__ obe,
                             float* __restrict__ out)
{
    int row = blockIdx.x, t = threadIdx.x;
    size_t base = (size_t)row*D;
    __shared__ float red[128];
    float v[4] = {0.f, 0.f, 0.f, 0.f};
    for (int n = 0; n < 8; n++) {
        if (g_processed[n]) continue;
        const float* p = g_outs + (size_t)n*NELEM + base;
        #pragma unroll
        for (int i = 0; i < 4; i++) v[i] += p[t + i*128];
    }
    float s = v[0]+v[1]+v[2]+v[3];
    red[t] = s; __syncthreads();
    for (int off = 64; off > 0; off >>= 1) { if (t < off) red[t] += red[t+off]; __syncthreads(); }
    float mean = red[0] / (float)D; __syncthreads();
    s = 0.f;
    #pragma unroll
    for (int i = 0; i < 4; i++) { float d = v[i]-mean; s += d*d; }
    red[t] = s; __syncthreads();
    for (int off = 64; off > 0; off >>= 1) { if (t < off) red[t] += red[t+off]; __syncthreads(); }
    float rs = rsqrtf(red[0] / (float)D + 1e-6f);
    #pragma unroll
    for (int i = 0; i < 4; i++) {
        int col = t + i*128;
        out[base + col] = (v[i]-mean)*rs*og[col] + obe[col];
    }
}

/* ------------------------------------------------------------------ */
extern "C" void kernel_launch(void* const* d_in, const int* in_sizes, int n_in,
                              void* d_out, int out_size)
{
    const float* inpute = (const float*)d_in[0];
    const float* inputo = (const float*)d_in[1];
    const float* node_p = (const float*)d_in[2];
    const float* edge_p = (const float*)d_in[3];
    const float* eW     = (const float*)d_in[4];
    const float* eb     = (const float*)d_in[5];
    const float* eg     = (const float*)d_in[6];
    const float* ebe    = (const float*)d_in[7];
    const float* nW     = (const float*)d_in[8];
    const float* nb     = (const float*)d_in[9];
    const float* ng     = (const float*)d_in[10];
    const float* nbe    = (const float*)d_in[11];
    const float* og     = (const float*)d_in[12];
    const float* obe    = (const float*)d_in[13];
    const unsigned char* srcm = (const unsigned char*)d_in[14];
    const unsigned char* tgtm = (const unsigned char*)d_in[15];
    float* out = (float*)d_out;

    route_kernel<<<1, 32>>>(node_p, edge_p);

    dim3 gg(8, 64);
    for (int c = 0; c < 8; c++) {
        for (int role = 0; role < 3; role++) {
            edge_prep_kernel<<<NTOK, 128>>>(c, role, inpute, inputo, eg, ebe);
            gemm_kernel<<<gg, 256>>>(c, role, eW, eb, nW, nb);
        }
        node_prep_kernel<<<NTOK, 128>>>(c, ng, nbe);
        for (int role = 3; role < 6; role++)
            gemm_kernel<<<gg, 256>>>(c, role, eW, eb, nW, nb);
        attn_scores_kernel<<<dim3(16, 16, 32), 256>>>(c, srcm, tgtm);
        attn_softmax_kernel<<<BATCH*NH*SEQ, 256>>>(c);
        attn_pv_kernel<<<dim3(16, 32), 256>>>(c);
        gemm_kernel<<<gg, 256>>>(c, 6, eW, eb, nW, nb);
        node_ew_kernel<<<NTOK, 128>>>(c);
    }
    final_kernel<<<NTOK, 128>>>(og, obe, out);
}

// round 2
// speedup vs baseline: 2.5728x; 2.5728x over previous
#include <cuda_runtime.h>
#include <math.h>
#include <stdint.h>
#include <stddef.h>

#define D      512
#define BATCH  4
#define SEQ    1024
#define NTOK   (BATCH*SEQ)          /* 4096 */
#define NEDGE  34
#define NH     8
#define DH     64
#define NELEM  ((size_t)NTOK*(size_t)D)

/* ------------------------------------------------------------------ */
struct Route {
    int nsrc, lind, snode, act;
    int q_sel, k_sel, v_sel;
    int ktype, vmode;
    float aw, wq, wk, wv;
    int q_e, q_op, q_inn;
    int k_e, k_op, k_inn;
    int v_e, v_op, v_inn;
};

__device__ Route g_routes[8];
__device__ int   g_processed[8];

__device__ float g_outs[8*NTOK*D];
__device__ float g_tq [NTOK*D];
__device__ float g_tk [NTOK*D];
__device__ float g_tv [NTOK*D];
__device__ float g_tln[NTOK*D];
__device__ float g_t0 [NTOK*D];
__device__ float g_t1 [NTOK*D];
__device__ float g_t2 [NTOK*D];
__device__ float g_prep[NTOK*D];
__device__ float g_scores[(size_t)BATCH*NH*SEQ*SEQ];

__device__ __forceinline__ float geluf(float x) {
    return 0.5f*x*(1.0f + tanhf(0.7978845608028654f*(x + 0.044715f*x*x*x)));
}
__device__ __forceinline__ float sigmoidf_(float x) {
    return 1.0f/(1.0f+expf(-x));
}
__device__ __forceinline__ uint32_t f2tf(float x) {
    uint32_t r; asm("cvt.rna.tf32.f32 %0, %1;" : "=r"(r) : "f"(x)); return r;
}
__device__ __forceinline__ float4 cvt4(float4 v) {
    v.x = __uint_as_float(f2tf(v.x)); v.y = __uint_as_float(f2tf(v.y));
    v.z = __uint_as_float(f2tf(v.z)); v.w = __uint_as_float(f2tf(v.w));
    return v;
}
__device__ __forceinline__ void mma_tf32(float* c, const uint32_t* a, const uint32_t* b) {
    asm volatile(
        "mma.sync.aligned.m16n8k8.row.col.f32.tf32.tf32.f32 "
        "{%0,%1,%2,%3},{%4,%5,%6,%7},{%8,%9},{%0,%1,%2,%3};\n"
        : "+f"(c[0]), "+f"(c[1]), "+f"(c[2]), "+f"(c[3])
        : "r"(a[0]), "r"(a[1]), "r"(a[2]), "r"(a[3]), "r"(b[0]), "r"(b[1]));
}

#define ASTR 36
#define BSTR 72

/* shared MMA inner block: As[128][ASTR] (m-major), Bs[32][BSTR] (k-major) */
__device__ __forceinline__ void mma_block(const float* As, const float* Bs,
                                          float acc[2][4][4],
                                          int wr, int wc, int gid, int tig)
{
    #pragma unroll
    for (int kk = 0; kk < 4; kk++) {
        uint32_t a[2][4];
        #pragma unroll
        for (int mi = 0; mi < 2; mi++) {
            const float* Ap = &As[(wr*32 + mi*16 + gid)*ASTR + kk*8 + tig];
            a[mi][0] = __float_as_uint(Ap[0]);
            a[mi][1] = __float_as_uint(Ap[8*ASTR]);
            a[mi][2] = __float_as_uint(Ap[4]);
            a[mi][3] = __float_as_uint(Ap[8*ASTR + 4]);
        }
        uint32_t b[4][2];
        #pragma unroll
        for (int ni = 0; ni < 4; ni++) {
            int col = wc*32 + ni*8 + gid;
            b[ni][0] = __float_as_uint(Bs[(kk*8 + tig)*BSTR + col]);
            b[ni][1] = __float_as_uint(Bs[(kk*8 + tig + 4)*BSTR + col]);
        }
        #pragma unroll
        for (int mi = 0; mi < 2; mi++)
            #pragma unroll
            for (int ni = 0; ni < 4; ni++)
                mma_tf32(acc[mi][ni], a[mi], b[ni]);
    }
}

/* ------------------------------------------------------------------ */
/* Routing kernel                                                      */
/* ------------------------------------------------------------------ */
__global__ void route_kernel(const float* __restrict__ node_p,
                             const float* __restrict__ edge_p)
{
    if (threadIdx.x != 0 || blockIdx.x != 0) return;
    for (int i = 0; i < 8; i++) g_processed[i] = 0;

    int lind = 0;
    for (int c = 0; c < 8; c++) {
        int nsrc  = (c + 2 < 5) ? c + 2 : 5;
        int snode = c - nsrc;
        int n5    = nsrc * 5;
        Route r;
        r.nsrc = nsrc; r.lind = lind; r.snode = snode;

        int act = 0; float bm = node_p[c*8];
        for (int a = 1; a < 8; a++) { float v = node_p[c*8+a]; if (v > bm) { bm = v; act = a; } }
        float ssum = 0.f;
        for (int a = 0; a < 8; a++) ssum += expf(node_p[c*8+a] - bm);
        r.act = act; r.aw = expf(node_p[c*8+act] - bm) / ssum;

        #define EPV(i,j) edge_p[(((i)*NEDGE) + lind + (j)/5)*5 + ((j)%5)]

        int qs = -1; float qb = 0.f;
        for (int j = 5; j < n5; j++) {
            float v = EPV(0,j);
            if (qs < 0 || v > qb) { qb = v; qs = j; }
        }
        {
            float s = 0.f;
            for (int j = 5; j < n5; j++) s += expf(EPV(0,j) - qb);
            r.wq = expf(EPV(0,qs) - qb) / s;
        }
        r.q_sel = qs;

        r.k_sel = -1; r.v_sel = -1; r.ktype = 0; r.vmode = 0; r.wk = 0.f; r.wv = 0.f;
        if (act < 7) {
            bool kmask = (act > 0);
            int ks = -1; float kb = 0.f;
            for (int j = 0; j < n5; j++) {
                if (kmask && j < 5) continue;
                float v = EPV(1,j);
                if (ks < 0 || v > kb) { kb = v; ks = j; }
            }
            r.k_sel = ks;
            r.ktype = (ks/5 == 0) ? -2 : -1;
            {
                float s = 0.f;
                for (int j = 0; j < n5; j++) {
                    if (kmask && j < 5) continue;
                    s += expf(EPV(1,j) - kb);
                }
                r.wk = expf(EPV(1,ks) - kb) / s;
            }
            if (act < 5) {
                if (act == 0 && r.ktype == -2) {
                    int vs = 0; float vb = EPV(2,0);
                    for (int j = 1; j < 5; j++) { float v = EPV(2,j); if (v > vb) { vb = v; vs = j; } }
                    float s = 0.f;
                    for (int j = 0; j < 5; j++) s += expf(EPV(2,j) - vb);
                    r.v_sel = vs; r.vmode = 1;
                    r.wv = expf(EPV(2,vs) - vb) / s;
                } else {
                    int vs = -1; float vb = 0.f;
                    for (int j = 0; j < n5; j++) {
                        if (kmask && j < 5) continue;
                        float v = EPV(2,j);
                        if (vs < 0 || v > vb) { vb = v; vs = j; }
                    }
                    float s = 0.f;
                    for (int j = 0; j < n5; j++) {
                        if (kmask && j < 5) continue;
                        s += expf(EPV(2,j) - vb);
                    }
                    r.v_sel = vs; r.vmode = 0;
                    r.wv = expf(EPV(2,vs) - vb) / s;
                }
            }
        }
        #undef EPV

        {
            int se = r.q_sel/5; r.q_op = r.q_sel%5; r.q_e = lind+se;
            r.q_inn = (se == 0) ? -2 : snode+se;
            if (r.q_inn >= 0) g_processed[r.q_inn] = 1;
        }
        if (r.k_sel >= 0) {
            int se = r.k_sel/5; r.k_op = r.k_sel%5; r.k_e = lind+se;
            r.k_inn = (se == 0) ? -2 : snode+se;
            if (r.k_inn >= 0) g_processed[r.k_inn] = 1;
        } else { r.k_e = 0; r.k_op = 4; r.k_inn = -2; }
        if (r.v_sel >= 0) {
            int se = r.v_sel/5; r.v_op = r.v_sel%5; r.v_e = lind+se;
            r.v_inn = (se == 0) ? -2 : snode+se;
            if (r.v_inn >= 0) g_processed[r.v_inn] = 1;
        } else { r.v_e = 0; r.v_op = 4; r.v_inn = -2; }

        g_routes[c] = r;
        lind += nsrc;
    }
}

/* ------------------------------------------------------------------ */
/* Edge prep: LN (ops 0-2) -> g_prep; op 4 scaled copy. op 3 skipped.  */
/* grid NTOK x 128                                                     */
/* ------------------------------------------------------------------ */
__global__ void edge_prep_kernel(int c, int role,
                                 const float* __restrict__ inpute,
                                 const float* __restrict__ inputo,
                                 const float* __restrict__ eg,
                                 const float* __restrict__ ebe)
{
    Route r = g_routes[c];
    int sel, e, op, inn; float w;
    if (role == 0)      { sel = r.q_sel; e = r.q_e; op = r.q_op; inn = r.q_inn; w = r.wq; }
    else if (role == 1) { sel = r.k_sel; e = r.k_e; op = r.k_op; inn = r.k_inn; w = r.wk; }
    else {
        sel = r.v_sel; e = r.v_e; op = r.v_op; inn = r.v_inn; w = r.wv;
        if (r.act == 1) return;
    }
    if (sel < 0 || op == 3) return;

    const float* src = (inn == -2) ? inpute : (inn == -1) ? inputo
                       : (g_outs + (size_t)inn*NELEM);
    int row = blockIdx.x, t = threadIdx.x;
    const float4* x4 = (const float4*)(src + (size_t)row*D);
    float4 v = x4[t];

    if (op == 4) {
        float4* o = (float4*)((((role == 0) ? g_tq : (role == 1) ? g_tk : g_tv)) + (size_t)row*D);
        v.x *= w; v.y *= w; v.z *= w; v.w *= w;
        o[t] = v;
        return;
    }
    /* ops 0..2: LN */
    __shared__ float sm[4];
    float s = v.x + v.y + v.z + v.w;
    #pragma unroll
    for (int off = 16; off > 0; off >>= 1) s += __shfl_xor_sync(0xffffffffu, s, off);
    if ((t & 31) == 0) sm[t >> 5] = s;
    __syncthreads();
    float mean = (sm[0]+sm[1]+sm[2]+sm[3]) * (1.f/(float)D);
    __syncthreads();
    float dx = v.x-mean, dy = v.y-mean, dz = v.z-mean, dw = v.w-mean;
    float s2 = dx*dx + dy*dy + dz*dz + dw*dw;
    #pragma unroll
    for (int off = 16; off > 0; off >>= 1) s2 += __shfl_xor_sync(0xffffffffu, s2, off);
    if ((t & 31) == 0) sm[t >> 5] = s2;
    __syncthreads();
    float rs = rsqrtf((sm[0]+sm[1]+sm[2]+sm[3]) * (1.f/(float)D) + 1e-6f);
    const float4 g4 = ((const float4*)(eg  + (size_t)e*D))[t];
    const float4 b4 = ((const float4*)(ebe + (size_t)e*D))[t];
    float4 o;
    o.x = dx*rs*g4.x + b4.x; o.y = dy*rs*g4.y + b4.y;
    o.z = dz*rs*g4.z + b4.z; o.w = dw*rs*g4.w + b4.w;
    ((float4*)(g_prep + (size_t)row*D))[t] = o;
}

/* ------------------------------------------------------------------ */
struct GCfg {
    int active;
    const float* A; const float* A2; int amode;   /* 0 plain, 1 relu, 2 A*A2 */
    const float* W; const float* bias;
    float* C; const float* resid;
    float scale; int act;                          /* 0 none, 1 relu, 2 gelu */
    int accum;
};

__device__ __forceinline__ GCfg gemm_cfg(int c, int role,
                                         const float* eW, const float* eb,
                                         const float* nW, const float* nb,
                                         const float* inpute, const float* inputo)
{
    Route r = g_routes[c];
    GCfg g; g.active = 0; g.amode = 0; g.act = 0; g.accum = 0;
    g.scale = 1.f; g.A2 = 0; g.resid = 0; g.bias = 0; g.A = 0; g.W = 0; g.C = 0;

    if (role < 3) {
        int sel, e, op, inn; float w;
        if (role == 0)      { sel = r.q_sel; e = r.q_e; op = r.q_op; inn = r.q_inn; w = r.wq; }
        else if (role == 1) { sel = r.k_sel; e = r.k_e; op = r.k_op; inn = r.k_inn; w = r.wk; }
        else {
            sel = r.v_sel; e = r.v_e; op = r.v_op; inn = r.v_inn; w = r.wv;
            if (r.act == 1) return g;
        }
        if (sel < 0 || op == 4) return g;
        g.active = 1;
        if (op == 3) {
            g.A = (inn == -2) ? inpute : (inn == -1) ? inputo : (g_outs + (size_t)inn*NELEM);
        } else {
            g.A = g_prep;
        }
        g.W = eW + (size_t)e*D*D;
        g.bias = eb + (size_t)e*D;
        g.act = (op == 0) ? 1 : (op == 1) ? 2 : 0;
        g.C = (role == 0) ? g_tq : (role == 1) ? g_tk : g_tv;
        g.scale = w;
        return g;
    }

    const float* W0 = nW + (size_t)c*4*D*D;
    const float* b0 = nb + (size_t)c*4*D;
    int a = r.act;
    if (role == 3) {
        if (a == 0)      { g.active=1; g.A=g_tln; g.W=W0;       g.bias=b0;       g.C=g_t0; }
        else if (a == 1) { g.active=1; g.A=g_tq;  g.W=W0;       g.bias=b0;       g.C=g_t0; g.act=2; }
        else if (a == 3) { g.active=1; g.A=g_tq;  g.W=W0;                        g.C=g_t0; }
    } else if (role == 4) {
        if (a == 0 || a == 1) { g.active=1; g.A=g_tk; g.W=W0+(size_t)D*D; g.bias=b0+D; g.C=g_t1; }
        else if (a == 3)      { g.active=1; g.A=g_tk; g.W=W0+(size_t)D*D;              g.C=g_t0; g.accum=1; }
        else if (a == 5)      { g.active=1; g.A=g_tk; g.W=W0+(size_t)D*D; g.bias=b0+D; g.C=g_t0; g.act=2; }
    } else if (role == 5) {
        if (a == 0)      { g.active=1; g.A=g_tv; g.W=W0+(size_t)2*D*D; g.bias=b0+2*D; g.C=g_t2; }
        else if (a == 3) { g.active=1; g.A=g_tv; g.W=W0+(size_t)2*D*D;                g.C=g_t0; g.accum=1; }
    } else {
        if (a == 0) {
            g.active=1; g.A=g_tln; g.W=W0+(size_t)3*D*D; g.bias=b0+3*D;
            g.C=g_outs+(size_t)c*NELEM; g.resid=g_tq; g.scale=r.aw;
        } else if (a == 1) {
            g.active=1; g.A=g_t0; g.amode=2; g.A2=g_t1; g.W=W0+(size_t)3*D*D; g.bias=b0+3*D;
            g.C=g_outs+(size_t)c*NELEM; g.resid=g_tq; g.scale=r.aw;
        } else if (a == 3) {
            g.active=1; g.A=g_t0; g.amode=1; g.W=W0+(size_t)3*D*D; g.bias=b0+3*D;
            g.C=g_outs+(size_t)c*NELEM; g.resid=g_tq; g.scale=r.aw;
        }
    }
    return g;
}

/* ------------------------------------------------------------------ */
/* tf32 MMA GEMM: M=4096, N=512, K=512; block tile 128x64, BK=32       */
/* grid (8, 32) x 256 threads                                          */
/* ------------------------------------------------------------------ */
__global__ __launch_bounds__(256, 2)
void gemm_tf32_kernel(int c, int role,
                      const float* __restrict__ eW, const float* __restrict__ eb,
                      const float* __restrict__ nW, const float* __restrict__ nb,
                      const float* __restrict__ inpute, const float* __restrict__ inputo)
{
    GCfg g = gemm_cfg(c, role, eW, eb, nW, nb, inpute, inputo);
    if (!g.active) return;

    __shared__ float As[128*ASTR];
    __shared__ float Bs[32*BSTR];
    int tid = threadIdx.x;
    int rowBase = blockIdx.y*128, colBase = blockIdx.x*64;
    int wid = tid>>5, lane = tid&31, gid = lane>>2, tig = lane&3;
    int wr = wid>>1, wc = wid&1;

    float acc[2][4][4];
    #pragma unroll
    for (int mi = 0; mi < 2; mi++)
        #pragma unroll
        for (int ni = 0; ni < 4; ni++)
            #pragma unroll
            for (int j = 0; j < 4; j++) acc[mi][ni][j] = 0.f;

    float4 ra[4], ra2[4], rb[2];

    /* prefetch k0 = 0 */
    #pragma unroll
    for (int i = 0; i < 4; i++) {
        int idx = tid + i*256, rr = idx>>3, kq = idx&7;
        ra[i] = *(const float4*)(g.A + (size_t)(rowBase+rr)*D + kq*4);
        if (g.amode == 2) ra2[i] = *(const float4*)(g.A2 + (size_t)(rowBase+rr)*D + kq*4);
    }
    #pragma unroll
    for (int i = 0; i < 2; i++) {
        int idx = tid + i*256, rr = idx>>4, nq = idx&15;
        rb[i] = *(const float4*)(g.W + (size_t)rr*D + colBase + nq*4);
    }

    for (int k0 = 0; k0 < D; k0 += 32) {
        /* regs -> smem (with activation-on-A + tf32 rounding) */
        #pragma unroll
        for (int i = 0; i < 4; i++) {
            int idx = tid + i*256, rr = idx>>3, kq = idx&7;
            float4 v = ra[i];
            if (g.amode == 1) {
                v.x = fmaxf(v.x,0.f); v.y = fmaxf(v.y,0.f);
                v.z = fmaxf(v.z,0.f); v.w = fmaxf(v.w,0.f);
            } else if (g.amode == 2) {
                v.x *= ra2[i].x; v.y *= ra2[i].y; v.z *= ra2[i].z; v.w *= ra2[i].w;
            }
            *(float4*)&As[rr*ASTR + kq*4] = cvt4(v);
        }
        #pragma unroll
        for (int i = 0; i < 2; i++) {
            int idx = tid + i*256, rr = idx>>4, nq = idx&15;
            *(float4*)&Bs[rr*BSTR + nq*4] = cvt4(rb[i]);
        }
        __syncthreads();

        if (k0 + 32 < D) {
            int kn = k0 + 32;
            #pragma unroll
            for (int i = 0; i < 4; i++) {
                int idx = tid + i*256, rr = idx>>3, kq = idx&7;
                ra[i] = *(const float4*)(g.A + (size_t)(rowBase+rr)*D + kn + kq*4);
                if (g.amode == 2) ra2[i] = *(const float4*)(g.A2 + (size_t)(rowBase+rr)*D + kn + kq*4);
            }
            #pragma unroll
            for (int i = 0; i < 2; i++) {
                int idx = tid + i*256, rr = idx>>4, nq = idx&15;
                rb[i] = *(const float4*)(g.W + (size_t)(kn+rr)*D + colBase + nq*4);
            }
        }

        mma_block(As, Bs, acc, wr, wc, gid, tig);
        __syncthreads();
    }

    /* epilogue */
    auto emit = [&](int rr, int cc, float v) {
        if (g.bias) v += g.bias[cc];
        if (g.act == 1) v = fmaxf(v, 0.f);
        else if (g.act == 2) v = geluf(v);
        size_t idx = (size_t)rr*D + cc;
        if (g.accum) g.C[idx] += v;
        else {
            if (g.resid) v += g.resid[idx];
            g.C[idx] = g.scale * v;
        }
    };
    #pragma unroll
    for (int mi = 0; mi < 2; mi++) {
        int r0 = rowBase + wr*32 + mi*16 + gid;
        #pragma unroll
        for (int ni = 0; ni < 4; ni++) {
            int cb = colBase + wc*32 + ni*8 + tig*2;
            emit(r0,   cb,   acc[mi][ni][0]);
            emit(r0,   cb+1, acc[mi][ni][1]);
            emit(r0+8, cb,   acc[mi][ni][2]);
            emit(r0+8, cb+1, acc[mi][ni][3]);
        }
    }
}

/* ------------------------------------------------------------------ */
/* Node prep: elementwise / LN acts. grid NTOK x 128                    */
/* ------------------------------------------------------------------ */
__global__ void node_prep_kernel(int c, const float* __restrict__ ng,
                                 const float* __restrict__ nbe)
{
    Route r = g_routes[c];
    int a = r.act;
    if (!(a == 0 || a == 2 || a == 4 || a == 6 || a == 7)) return;
    int row = blockIdx.x, t = threadIdx.x;
    size_t base = (size_t)row*D;

    const float4* q4 = (const float4*)(g_tq + base);
    const float4* k4 = (const float4*)(g_tk + base);
    const float4* v4 = (const float4*)(g_tv + base);
    float4* o4 = (float4*)(g_outs + (size_t)c*NELEM + base);

    if (a == 4) {
        float4 q = q4[t], k = k4[t], vv = v4[t], o;
        o.x = r.aw*(q.x*sigmoidf_(k.x)+vv.x); o.y = r.aw*(q.y*sigmoidf_(k.y)+vv.y);
        o.z = r.aw*(q.z*sigmoidf_(k.z)+vv.z); o.w = r.aw*(q.w*sigmoidf_(k.w)+vv.w);
        o4[t] = o;
        return;
    }
    if (a == 6) {
        float4 q = q4[t], k = k4[t], o;
        o.x = r.aw*(q.x+k.x); o.y = r.aw*(q.y+k.y);
        o.z = r.aw*(q.z+k.z); o.w = r.aw*(q.w+k.w);
        o4[t] = o;
        return;
    }
    /* LN cases */
    __shared__ float sm[4];
    float4 x = q4[t];
    if (a == 2) {
        float4 k = k4[t], vv = v4[t];
        x.x += k.x+vv.x; x.y += k.y+vv.y; x.z += k.z+vv.z; x.w += k.w+vv.w;
    }
    float s = x.x+x.y+x.z+x.w;
    #pragma unroll
    for (int off = 16; off > 0; off >>= 1) s += __shfl_xor_sync(0xffffffffu, s, off);
    if ((t&31) == 0) sm[t>>5] = s;
    __syncthreads();
    float mean = (sm[0]+sm[1]+sm[2]+sm[3]) * (1.f/(float)D);
    __syncthreads();
    float dx = x.x-mean, dy = x.y-mean, dz = x.z-mean, dw = x.w-mean;
    float s2 = dx*dx+dy*dy+dz*dz+dw*dw;
    #pragma unroll
    for (int off = 16; off > 0; off >>= 1) s2 += __shfl_xor_sync(0xffffffffu, s2, off);
    if ((t&31) == 0) sm[t>>5] = s2;
    __syncthreads();
    float rs = rsqrtf((sm[0]+sm[1]+sm[2]+sm[3]) * (1.f/(float)D) + 1e-6f);
    const float4 g4 = ((const float4*)(ng  + (size_t)c*D))[t];
    const float4 b4 = ((const float4*)(nbe + (size_t)c*D))[t];
    float4 o;
    o.x = dx*rs*g4.x + b4.x; o.y = dy*rs*g4.y + b4.y;
    o.z = dz*rs*g4.z + b4.z; o.w = dw*rs*g4.w + b4.w;
    if (a == 0) ((float4*)(g_tln + base))[t] = o;
    else {
        o.x *= r.aw; o.y *= r.aw; o.z *= r.aw; o.w *= r.aw;
        o4[t] = o;
    }
}

__global__ void node_ew_kernel(int c)
{
    Route r = g_routes[c];
    if (r.act != 5) return;
    int row = blockIdx.x, t = threadIdx.x;
    size_t base = (size_t)row*D;
    float4 q = ((const float4*)(g_tq + base))[t];
    float4 h = ((const float4*)(g_t0 + base))[t];
    float4 o;
    o.x = r.aw*(q.x+h.x); o.y = r.aw*(q.y+h.y);
    o.z = r.aw*(q.z+h.z); o.w = r.aw*(q.w+h.w);
    ((float4*)(g_outs + (size_t)c*NELEM + base))[t] = o;
}

/* ------------------------------------------------------------------ */
/* Attention scores: tf32 MMA, tile 128x64, K=64. grid (16,8,32)       */
/* ------------------------------------------------------------------ */
__global__ __launch_bounds__(256, 2)
void attn_scores_kernel(int c,
                        const unsigned char* __restrict__ srcm,
                        const unsigned char* __restrict__ tgtm)
{
    Route r = g_routes[c];
    if (r.act != 0) return;
    int bh = blockIdx.z, b = bh>>3, h = bh&7;
    const float* Q = g_t0 + (size_t)b*SEQ*D + (size_t)h*DH;
    const float* K = g_t1 + (size_t)b*SEQ*D + (size_t)h*DH;
    const unsigned char* m = ((r.ktype == -2) ? srcm : tgtm) + (size_t)b*SEQ;

    __shared__ float As[128*ASTR];
    __shared__ float Bs[32*BSTR];
    int tid = threadIdx.x;
    int rowBase = blockIdx.y*128, colBase = blockIdx.x*64;
    int wid = tid>>5, lane = tid&31, gid = lane>>2, tig = lane&3;
    int wr = wid>>1, wc = wid&1;

    float acc[2][4][4];
    #pragma unroll
    for (int mi = 0; mi < 2; mi++)
        #pragma unroll
        for (int ni = 0; ni < 4; ni++)
            #pragma unroll
            for (int j = 0; j < 4; j++) acc[mi][ni][j] = 0.f;

    #pragma unroll
    for (int k0 = 0; k0 < DH; k0 += 32) {
        #pragma unroll
        for (int i = 0; i < 4; i++) {
            int idx = tid + i*256, rr = idx>>3, kq = idx&7;
            float4 v = *(const float4*)(Q + (size_t)(rowBase+rr)*D + k0 + kq*4);
            *(float4*)&As[rr*ASTR + kq*4] = cvt4(v);
        }
        #pragma unroll
        for (int i = 0; i < 8; i++) {
            int idx = tid + i*256, ss = idx>>5, dl = idx&31;
            Bs[dl*BSTR + ss] = __uint_as_float(f2tf(K[(size_t)(colBase+ss)*D + k0 + dl]));
        }
        __syncthreads();
        mma_block(As, Bs, acc, wr, wc, gid, tig);
        __syncthreads();
    }

    float* Sp = g_scores + (size_t)bh*SEQ*SEQ;
    auto emit = [&](int rr, int cc, float v) {
        v *= 0.125f;
        if (m[cc]) v = -1e9f;
        Sp[(size_t)rr*SEQ + cc] = v;
    };
    #pragma unroll
    for (int mi = 0; mi < 2; mi++) {
        int r0 = rowBase + wr*32 + mi*16 + gid;
        #pragma unroll
        for (int ni = 0; ni < 4; ni++) {
            int cb = colBase + wc*32 + ni*8 + tig*2;
            emit(r0,   cb,   acc[mi][ni][0]);
            emit(r0,   cb+1, acc[mi][ni][1]);
            emit(r0+8, cb,   acc[mi][ni][2]);
            emit(r0+8, cb+1, acc[mi][ni][3]);
        }
    }
}

/* grid 32768 x 256: softmax over rows of 1024 */
__global__ void attn_softmax_kernel(int c)
{
    if (g_routes[c].act != 0) return;
    size_t row = blockIdx.x;
    float4* p = (float4*)(g_scores + row*(size_t)SEQ);
    int t = threadIdx.x;
    __shared__ float sm[8];
    float4 v = p[t];
    float mx = fmaxf(fmaxf(v.x,v.y), fmaxf(v.z,v.w));
    #pragma unroll
    for (int off = 16; off > 0; off >>= 1) mx = fmaxf(mx, __shfl_xor_sync(0xffffffffu, mx, off));
    if ((t&31) == 0) sm[t>>5] = mx;
    __syncthreads();
    float M = sm[0];
    #pragma unroll
    for (int i = 1; i < 8; i++) M = fmaxf(M, sm[i]);
    __syncthreads();
    float4 e;
    e.x = expf(v.x-M); e.y = expf(v.y-M); e.z = expf(v.z-M); e.w = expf(v.w-M);
    float s = e.x+e.y+e.z+e.w;
    #pragma unroll
    for (int off = 16; off > 0; off >>= 1) s += __shfl_xor_sync(0xffffffffu, s, off);
    if ((t&31) == 0) sm[t>>5] = s;
    __syncthreads();
    float tot = 0.f;
    #pragma unroll
    for (int i = 0; i < 8; i++) tot += sm[i];
    float inv = 1.0f / tot;
    e.x *= inv; e.y *= inv; e.z *= inv; e.w *= inv;
    p[t] = e;
}

/* P·V: tile 128x64, K=1024. grid (1,8,32) */
__global__ __launch_bounds__(256, 2)
void attn_pv_kernel(int c)
{
    Route r = g_routes[c];
    if (r.act != 0) return;
    int bh = blockIdx.z, b = bh>>3, h = bh&7;
    int rowBase = blockIdx.y*128;
    const float* P = g_scores + (size_t)bh*SEQ*SEQ;
    const float* V = g_t2 + (size_t)b*SEQ*D + (size_t)h*DH;

    __shared__ float As[128*ASTR];
    __shared__ float Bs[32*BSTR];
    int tid = threadIdx.x;
    int wid = tid>>5, lane = tid&31, gid = lane>>2, tig = lane&3;
    int wr = wid>>1, wc = wid&1;

    float acc[2][4][4];
    #pragma unroll
    for (int mi = 0; mi < 2; mi++)
        #pragma unroll
        for (int ni = 0; ni < 4; ni++)
            #pragma unroll
            for (int j = 0; j < 4; j++) acc[mi][ni][j] = 0.f;

    float4 ra[4], rb[2];
    #pragma unroll
    for (int i = 0; i < 4; i++) {
        int idx = tid + i*256, rr = idx>>3, kq = idx&7;
        ra[i] = *(const float4*)(P + (size_t)(rowBase+rr)*SEQ + kq*4);
    }
    #pragma unroll
    for (int i = 0; i < 2; i++) {
        int idx = tid + i*256, rr = idx>>4, nq = idx&15;
        rb[i] = *(const float4*)(V + (size_t)rr*D + nq*4);
    }

    for (int k0 = 0; k0 < SEQ; k0 += 32) {
        #pragma unroll
        for (int i = 0; i < 4; i++) {
            int idx = tid + i*256, rr = idx>>3, kq = idx&7;
            *(float4*)&As[rr*ASTR + kq*4] = cvt4(ra[i]);
        }
        #pragma unroll
        for (int i = 0; i < 2; i++) {
            int idx = tid + i*256, rr = idx>>4, nq = idx&15;
            *(float4*)&Bs[rr*BSTR + nq*4] = cvt4(rb[i]);
        }
        __syncthreads();
        if (k0 + 32 < SEQ) {
            int kn = k0 + 32;
            #pragma unroll
            for (int i = 0; i < 4; i++) {
                int idx = tid + i*256, rr = idx>>3, kq = idx&7;
                ra[i] = *(const float4*)(P + (size_t)(rowBase+rr)*SEQ + kn + kq*4);
            }
            #pragma unroll
            for (int i = 0; i < 2; i++) {
                int idx = tid + i*256, rr = idx>>4, nq = idx&15;
                rb[i] = *(const float4*)(V + (size_t)(kn+rr)*D + nq*4);
            }
        }
        mma_block(As, Bs, acc, wr, wc, gid, tig);
        __syncthreads();
    }

    float* O = g_tln + (size_t)b*SEQ*D + (size_t)h*DH;
    #pragma unroll
    for (int mi = 0; mi < 2; mi++) {
        int r0 = rowBase + wr*32 + mi*16 + gid;
        #pragma unroll
        for (int ni = 0; ni < 4; ni++) {
            int cb = wc*32 + ni*8 + tig*2;
            O[(size_t)r0*D + cb]       = acc[mi][ni][0];
            O[(size_t)r0*D + cb+1]     = acc[mi][ni][1];
            O[(size_t)(r0+8)*D + cb]   = acc[mi][ni][2];
            O[(size_t)(r0+8)*D + cb+1] = acc[mi][ni][3];
        }
    }
}

/* ------------------------------------------------------------------ */
__global__ void final_kernel(const float* __restrict__ og,
                             const float* __restrict__ obe,
                             float* __restrict__ out)
{
    int row = blockIdx.x, t = threadIdx.x;
    size_t base = (size_t)row*D;
    __shared__ float sm[4];
    float4 v = make_float4(0.f,0.f,0.f,0.f);
    for (int n = 0; n < 8; n++) {
        if (g_processed[n]) continue;
        float4 p = ((const float4*)(g_outs + (size_t)n*NELEM + base))[t];
        v.x += p.x; v.y += p.y; v.z += p.z; v.w += p.w;
    }
    float s = v.x+v.y+v.z+v.w;
    #pragma unroll
    for (int off = 16; off > 0; off >>= 1) s += __shfl_xor_sync(0xffffffffu, s, off);
    if ((t&31) == 0) sm[t>>5] = s;
    __syncthreads();
    float mean = (sm[0]+sm[1]+sm[2]+sm[3]) * (1.f/(float)D);
    __syncthreads();
    float dx = v.x-mean, dy = v.y-mean, dz = v.z-mean, dw = v.w-mean;
    float s2 = dx*dx+dy*dy+dz*dz+dw*dw;
    #pragma unroll
    for (int off = 16; off > 0; off >>= 1) s2 += __shfl_xor_sync(0xffffffffu, s2, off);
    if ((t&31) == 0) sm[t>>5] = s2;
    __syncthreads();
    float rs = rsqrtf((sm[0]+sm[1]+sm[2]+sm[3]) * (1.f/(float)D) + 1e-6f);
    const float4 g4 = ((const float4*)og)[t];
    const float4 b4 = ((const float4*)obe)[t];
    float4 o;
    o.x = dx*rs*g4.x + b4.x; o.y = dy*rs*g4.y + b4.y;
    o.z = dz*rs*g4.z + b4.z; o.w = dw*rs*g4.w + b4.w;
    ((float4*)(out + base))[t] = o;
}

/* ------------------------------------------------------------------ */
extern "C" void kernel_launch(void* const* d_in, const int* in_sizes, int n_in,
                              void* d_out, int out_size)
{
    const float* inpute = (const float*)d_in[0];
    const float* inputo = (const float*)d_in[1];
    const float* node_p = (const float*)d_in[2];
    const float* edge_p = (const float*)d_in[3];
    const float* eW     = (const float*)d_in[4];
    const float* eb     = (const float*)d_in[5];
    const float* eg     = (const float*)d_in[6];
    const float* ebe    = (const float*)d_in[7];
    const float* nW     = (const float*)d_in[8];
    const float* nb     = (const float*)d_in[9];
    const float* ng     = (const float*)d_in[10];
    const float* nbe    = (const float*)d_in[11];
    const float* og     = (const float*)d_in[12];
    const float* obe    = (const float*)d_in[13];
    const unsigned char* srcm = (const unsigned char*)d_in[14];
    const unsigned char* tgtm = (const unsigned char*)d_in[15];
    float* out = (float*)d_out;

    route_kernel<<<1, 32>>>(node_p, edge_p);

    dim3 gdense(8, 32);
    for (int c = 0; c < 8; c++) {
        for (int role = 0; role < 3; role++) {
            edge_prep_kernel<<<NTOK, 128>>>(c, role, inpute, inputo, eg, ebe);
            gemm_tf32_kernel<<<gdense, 256>>>(c, role, eW, eb, nW, nb, inpute, inputo);
        }
        node_prep_kernel<<<NTOK, 128>>>(c, ng, nbe);
        for (int role = 3; role < 6; role++)
            gemm_tf32_kernel<<<gdense, 256>>>(c, role, eW, eb, nW, nb, inpute, inputo);
        attn_scores_kernel<<<dim3(16, 8, 32), 256>>>(c, srcm, tgtm);
        attn_softmax_kernel<<<BATCH*NH*SEQ, 256>>>(c);
        attn_pv_kernel<<<dim3(1, 8, 32), 256>>>(c);
        gemm_tf32_kernel<<<gdense, 256>>>(c, 6, eW, eb, nW, nb, inpute, inputo);
        node_ew_kernel<<<NTOK, 128>>>(c);
    }
    final_kernel<<<NTOK, 128>>>(og, obe, out);
}